// round 1
// baseline (speedup 1.0000x reference)
#include <cuda_runtime.h>
#include <cstdint>
#include <cstddef>

// Problem constants
#define T_STEPS 2048
#define BATCH   64
#define IN_DIM  256
#define HID     512

// ---------------- scratch (device globals; no runtime allocation) ----------
__device__ float    g_xproj[(size_t)T_STEPS * BATCH * HID]; // 256 MiB
__device__ float    g_h[2][BATCH * HID];
__device__ unsigned g_bar;

// ---------------- init: zero h0 and barrier counter -------------------------
__global__ void rnn_init_kernel() {
    int idx = blockIdx.x * blockDim.x + threadIdx.x;
    if (idx == 0) g_bar = 0u;
    if (idx < BATCH * HID) g_h[0][idx] = 0.0f;
}

// ---------------- Phase A: x_proj GEMM --------------------------------------
// C[M,N] = A[M,K] * B[K,N];  M = T*B = 131072, K = 256, N = 512
#define GBM 64
#define GBN 64
#define GBK 32
#define GTM 4
#define GTN 4

__global__ __launch_bounds__(256) void xproj_gemm_kernel(
    const float* __restrict__ A, const float* __restrict__ B)
{
    __shared__ float As[GBK][GBM];   // transposed: As[k][m]
    __shared__ float Bs[GBK][GBN];

    const int tid = threadIdx.x;
    const int tx = tid % 16;          // n direction (4 each)
    const int ty = tid / 16;          // m direction (4 each)
    const size_t mBase = (size_t)blockIdx.y * GBM;
    const int    nBase = blockIdx.x * GBN;

    float acc[GTM][GTN];
#pragma unroll
    for (int i = 0; i < GTM; i++)
#pragma unroll
        for (int j = 0; j < GTN; j++) acc[i][j] = 0.0f;

    for (int kt = 0; kt < IN_DIM; kt += GBK) {
        // load A tile 64x32 (transpose into As[k][m])
#pragma unroll
        for (int s = 0; s < 2; s++) {
            int row = tid / 8 + s * 32;       // 0..63
            int k4  = (tid % 8) * 4;          // 0..28
            float4 v = *(const float4*)&A[(mBase + row) * IN_DIM + kt + k4];
            As[k4 + 0][row] = v.x;
            As[k4 + 1][row] = v.y;
            As[k4 + 2][row] = v.z;
            As[k4 + 3][row] = v.w;
        }
        // load B tile 32x64
#pragma unroll
        for (int s = 0; s < 2; s++) {
            int row = tid / 16 + s * 16;      // 0..31
            int n4  = (tid % 16) * 4;         // 0..60
            *(float4*)&Bs[row][n4] =
                *(const float4*)&B[(size_t)(kt + row) * HID + nBase + n4];
        }
        __syncthreads();

#pragma unroll
        for (int k = 0; k < GBK; k++) {
            float a[GTM], b[GTN];
            *(float4*)a = *(const float4*)&As[k][ty * GTM];
            *(float4*)b = *(const float4*)&Bs[k][tx * GTN];
#pragma unroll
            for (int i = 0; i < GTM; i++)
#pragma unroll
                for (int j = 0; j < GTN; j++)
                    acc[i][j] += a[i] * b[j];
        }
        __syncthreads();
    }

#pragma unroll
    for (int i = 0; i < GTM; i++) {
        size_t row = mBase + ty * GTM + i;
        float4 v = make_float4(acc[i][0], acc[i][1], acc[i][2], acc[i][3]);
        *(float4*)&g_xproj[row * HID + nBase + tx * GTN] = v;
    }
}

// ---------------- Phase B: persistent sequential scan -----------------------
// grid = (B/BTILE) * (H/JTILE) = 8 * 16 = 128 CTAs, 256 threads each.
// Each CTA: btile=8 batches x jtile=32 hidden columns.
// w_rec slice kept transposed (+pad) in smem for all 2048 steps.
#define BTILE 8
#define JTILE 32
#define N_BT  (BATCH / BTILE)    // 8
#define N_JT  (HID / JTILE)      // 16
#define SCAN_GRID (N_BT * N_JT)  // 128
#define WT_STRIDE 520            // 512 + 8 pad (avoids LDS conflicts, f4-aligned)
#define SCAN_SMEM_FLOATS (JTILE * WT_STRIDE + BTILE * HID)
#define SCAN_SMEM_BYTES  (SCAN_SMEM_FLOATS * 4)

__global__ __launch_bounds__(256, 1) void rnn_scan_kernel(
    const float* __restrict__ w_rec, float* __restrict__ out, int write_last)
{
    extern __shared__ float smem[];
    float* wT  = smem;                       // [JTILE][WT_STRIDE]
    float* h_s = smem + JTILE * WT_STRIDE;   // [BTILE][HID]

    const int tid = threadIdx.x;
    const int b   = tid >> 5;                // 0..7 (warp-uniform)
    const int j   = tid & 31;                // 0..31
    const int bt0 = (blockIdx.x / N_JT) * BTILE;
    const int j0  = (blockIdx.x % N_JT) * JTILE;

    // One-time: load transposed w_rec slice into smem. wT[j][k] = w_rec[k][j0+j]
    for (int idx = tid; idx < JTILE * HID; idx += 256) {
        int jj = idx / HID;
        int kk = idx - jj * HID;
        wT[jj * WT_STRIDE + kk] = w_rec[(size_t)kk * HID + j0 + jj];
    }
    __syncthreads();

    const int gidx = (bt0 + b) * HID + j0 + j;          // index within [B,H]
    const float4* wp = (const float4*)(wT + j * WT_STRIDE);

    for (int t = 0; t < T_STEPS; t++) {
        const int p = t & 1;

        // load h slice [BTILE x HID] = 1024 float4; bypass L1 (cross-SM producer)
        {
            const float4* hsrc = (const float4*)(&g_h[p][bt0 * HID]);
            float4* hdst = (float4*)h_s;
#pragma unroll
            for (int i = 0; i < 4; i++)
                hdst[tid + 256 * i] = __ldcg(hsrc + tid + 256 * i);
        }
        __syncthreads();

        float xv = g_xproj[(size_t)t * (BATCH * HID) + gidx];

        const float4* hp = (const float4*)(h_s + b * HID);
        float a0 = 0.f, a1 = 0.f, a2 = 0.f, a3 = 0.f;
#pragma unroll 8
        for (int k4 = 0; k4 < HID / 4; k4++) {
            float4 h4 = hp[k4];
            float4 w4 = wp[k4];
            a0 += h4.x * w4.x;
            a1 += h4.y * w4.y;
            a2 += h4.z * w4.z;
            a3 += h4.w * w4.w;
        }
        float hn = tanhf(xv + ((a0 + a1) + (a2 + a3)));

        g_h[p ^ 1][gidx] = hn;
        out[(size_t)t * (BATCH * HID) + gidx] = hn;
        if (write_last && t == T_STEPS - 1)
            out[(size_t)T_STEPS * (BATCH * HID) + gidx] = hn;

        // ---- global barrier (all 128 CTAs co-resident: 1 CTA/SM) ----
        __threadfence();
        __syncthreads();
        if (tid == 0) {
            unsigned tgt = (unsigned)SCAN_GRID * (unsigned)(t + 1);
            atomicAdd(&g_bar, 1u);
            unsigned v;
            do {
                asm volatile("ld.acquire.gpu.global.u32 %0, [%1];"
                             : "=r"(v) : "l"(&g_bar));
            } while (v < tgt);
        }
        __syncthreads();
    }
}

// ---------------- launch ----------------------------------------------------
extern "C" void kernel_launch(void* const* d_in, const int* in_sizes, int n_in,
                              void* d_out, int out_size)
{
    const float* input = (const float*)d_in[0];   // [T,B,I]
    const float* w_in  = (const float*)d_in[1];   // [I,H]
    const float* w_rec = (const float*)d_in[2];   // [H,H]
    float* out = (float*)d_out;

    int write_last =
        ((size_t)out_size >= (size_t)T_STEPS * BATCH * HID + (size_t)BATCH * HID)
            ? 1 : 0;

    cudaFuncSetAttribute(rnn_scan_kernel,
                         cudaFuncAttributeMaxDynamicSharedMemorySize,
                         SCAN_SMEM_BYTES);

    // zero h0 + barrier
    rnn_init_kernel<<<(BATCH * HID + 255) / 256, 256>>>();

    // x_proj big GEMM
    {
        dim3 grid(HID / GBN, (T_STEPS * BATCH) / GBM);  // (8, 2048)
        xproj_gemm_kernel<<<grid, 256>>>(input, w_in);
    }

    // persistent sequential scan
    rnn_scan_kernel<<<SCAN_GRID, 256, SCAN_SMEM_BYTES>>>(w_rec, out, write_last);
}

// round 2
// speedup vs baseline: 1.8121x; 1.8121x over previous
#include <cuda_runtime.h>
#include <cstdint>
#include <cstddef>

// Problem constants
#define T_STEPS 2048
#define BATCH   64
#define IN_DIM  256
#define HID     512
#define BH      (BATCH * HID)

// ---------------- scratch (device global; no runtime allocation) -----------
__device__ float g_xproj[(size_t)T_STEPS * BH]; // 256 MiB

// ---------------- Phase A: x_proj GEMM --------------------------------------
// C[M,N] = A[M,K] * B[K,N];  M = T*B = 131072, K = 256, N = 512
#define GBM 64
#define GBN 64
#define GBK 32
#define GTM 4
#define GTN 4

__global__ __launch_bounds__(256) void xproj_gemm_kernel(
    const float* __restrict__ A, const float* __restrict__ B)
{
    __shared__ float As[GBK][GBM];   // transposed: As[k][m]
    __shared__ float Bs[GBK][GBN];

    const int tid = threadIdx.x;
    const int tx = tid % 16;
    const int ty = tid / 16;
    const size_t mBase = (size_t)blockIdx.y * GBM;
    const int    nBase = blockIdx.x * GBN;

    float acc[GTM][GTN];
#pragma unroll
    for (int i = 0; i < GTM; i++)
#pragma unroll
        for (int j = 0; j < GTN; j++) acc[i][j] = 0.0f;

    for (int kt = 0; kt < IN_DIM; kt += GBK) {
#pragma unroll
        for (int s = 0; s < 2; s++) {
            int row = tid / 8 + s * 32;
            int k4  = (tid % 8) * 4;
            float4 v = *(const float4*)&A[(mBase + row) * IN_DIM + kt + k4];
            As[k4 + 0][row] = v.x;
            As[k4 + 1][row] = v.y;
            As[k4 + 2][row] = v.z;
            As[k4 + 3][row] = v.w;
        }
#pragma unroll
        for (int s = 0; s < 2; s++) {
            int row = tid / 16 + s * 16;
            int n4  = (tid % 16) * 4;
            *(float4*)&Bs[row][n4] =
                *(const float4*)&B[(size_t)(kt + row) * HID + nBase + n4];
        }
        __syncthreads();

#pragma unroll
        for (int k = 0; k < GBK; k++) {
            float a[GTM], b[GTN];
            *(float4*)a = *(const float4*)&As[k][ty * GTM];
            *(float4*)b = *(const float4*)&Bs[k][tx * GTN];
#pragma unroll
            for (int i = 0; i < GTM; i++)
#pragma unroll
                for (int j = 0; j < GTN; j++)
                    acc[i][j] += a[i] * b[j];
        }
        __syncthreads();
    }

#pragma unroll
    for (int i = 0; i < GTM; i++) {
        size_t row = mBase + ty * GTM + i;
        float4 v = make_float4(acc[i][0], acc[i][1], acc[i][2], acc[i][3]);
        *(float4*)&g_xproj[row * HID + nBase + tx * GTN] = v;
    }
}

// ---------------- Phase B: cluster-parallel sequential scan -----------------
// 16 independent clusters of 8 CTAs. Cluster c owns batches [4c, 4c+4) for the
// whole scan (batches never interact). CTA r in the cluster owns hidden
// columns [64r, 64r+64) and keeps its 512x64 w_rec slice resident in smem.
// Per step: split-K register-tiled partial GEMM (thread = (kc,jg) computes a
// 4b x 4j tile over a 32-wide k chunk), smem reduction over 16 k-chunks,
// tanh, then DSMEM broadcast of the 256 new h values to all 8 CTAs,
// one cluster barrier per step. No global memory in the recurrence path.
#define CLS  8               // cluster size (CTAs)
#define BPC  4               // batches per cluster
#define JPC  64              // hidden columns per CTA
#define HPAD 516             // padded h row stride (floats, 16B-aligned)
#define NKC  16              // k-chunks (split-K factor)
#define KC   (HID / NKC)     // 32 k per chunk

#define WS_FLOATS  (HID * JPC)        // 32768 (128 KB) w slice
#define HS_FLOATS  (2 * BPC * HPAD)   // 4128  double-buffered h
#define RED_FLOATS (NKC * 256)        // 4096  reduction buffer
#define SCAN_SMEM_BYTES ((WS_FLOATS + HS_FLOATS + RED_FLOATS) * 4)

__device__ __forceinline__ void cluster_sync_() {
    asm volatile("barrier.cluster.arrive.aligned;" ::: "memory");
    asm volatile("barrier.cluster.wait.aligned;"   ::: "memory");
}

__global__ __launch_bounds__(256, 1) __cluster_dims__(CLS, 1, 1)
void rnn_scan_kernel(const float* __restrict__ w_rec,
                     float* __restrict__ out, int write_last)
{
    extern __shared__ float smem[];
    float* ws  = smem;                         // [HID][JPC]
    float* hs  = smem + WS_FLOATS;             // [2][BPC][HPAD]
    float* red = smem + WS_FLOATS + HS_FLOATS; // [NKC][256]

    const int tid  = threadIdx.x;
    const int rank = blockIdx.x & (CLS - 1);       // CTA rank in cluster
    const int b0   = (blockIdx.x >> 3) * BPC;      // first batch of cluster
    const int j0   = rank * JPC;                   // first hidden col of CTA

    // roles
    const int kc = tid >> 4;      // 0..15  k-chunk
    const int jg = tid & 15;      // 0..15  j-group (4 cols each)
    const int ob = tid >> 6;      // 0..3   output batch   (o = tid)
    const int oj = tid & 63;      // 0..63  output column

    // ---- prologue: load w slice (coalesced), zero h buffer 0 ----
    {
        const float4* wsrc = (const float4*)w_rec;
        float4* wdst = (float4*)ws;
        // ws[k][jc] = w_rec[k][j0+jc] ; rows of 64 floats = 16 float4
        for (int i = tid; i < HID * (JPC / 4); i += 256) {
            int row = i >> 4;          // k
            int c4  = i & 15;
            wdst[row * 16 + c4] = wsrc[row * (HID / 4) + (j0 >> 2) + c4];
        }
        for (int i = tid; i < HS_FLOATS; i += 256) hs[i] = 0.0f;
    }
    __syncthreads();
    cluster_sync_();   // peers' smem initialized before any remote store

    const unsigned hs_u32 =
        (unsigned)__cvta_generic_to_shared(hs);

    const float* wrow = ws + (kc * KC) * JPC + jg * 4;

    for (int t = 0; t < T_STEPS; t++) {
        const int p = t & 1;
        const float* hp = hs + p * BPC * HPAD + kc * KC;

        // prefetch this step's input projection (independent of recurrence)
        float xv = __ldg(&g_xproj[(size_t)t * BH + (b0 + ob) * HID + j0 + oj]);

        // ---- split-K register-tiled partial products ----
        float acc[BPC][4];
#pragma unroll
        for (int b = 0; b < BPC; b++)
#pragma unroll
            for (int j = 0; j < 4; j++) acc[b][j] = 0.0f;

#pragma unroll
        for (int ki = 0; ki < KC; ki += 4) {
            float4 w0 = *(const float4*)(wrow + (ki + 0) * JPC);
            float4 w1 = *(const float4*)(wrow + (ki + 1) * JPC);
            float4 w2 = *(const float4*)(wrow + (ki + 2) * JPC);
            float4 w3 = *(const float4*)(wrow + (ki + 3) * JPC);
#pragma unroll
            for (int b = 0; b < BPC; b++) {
                float4 h4 = *(const float4*)(hp + b * HPAD + ki);
                acc[b][0] += h4.x * w0.x; acc[b][1] += h4.x * w0.y;
                acc[b][2] += h4.x * w0.z; acc[b][3] += h4.x * w0.w;
                acc[b][0] += h4.y * w1.x; acc[b][1] += h4.y * w1.y;
                acc[b][2] += h4.y * w1.z; acc[b][3] += h4.y * w1.w;
                acc[b][0] += h4.z * w2.x; acc[b][1] += h4.z * w2.y;
                acc[b][2] += h4.z * w2.z; acc[b][3] += h4.z * w2.w;
                acc[b][0] += h4.w * w3.x; acc[b][1] += h4.w * w3.y;
                acc[b][2] += h4.w * w3.z; acc[b][3] += h4.w * w3.w;
            }
        }

        __syncthreads();   // previous step's reduction reads are done
#pragma unroll
        for (int b = 0; b < BPC; b++)
            *(float4*)&red[kc * 256 + b * 64 + jg * 4] =
                make_float4(acc[b][0], acc[b][1], acc[b][2], acc[b][3]);
        __syncthreads();

        // ---- reduce over 16 k-chunks, activate ----
        float s = 0.0f;
#pragma unroll
        for (int c = 0; c < NKC; c++) s += red[c * 256 + tid];
        float hn = tanhf(xv + s);

        out[(size_t)t * BH + (b0 + ob) * HID + j0 + oj] = hn;
        if (write_last && t == T_STEPS - 1)
            out[(size_t)T_STEPS * BH + (b0 + ob) * HID + j0 + oj] = hn;

        // ---- broadcast h value into every cluster CTA's next buffer ----
        unsigned hdst = hs_u32 +
            (unsigned)(((p ^ 1) * BPC * HPAD + ob * HPAD + j0 + oj) * 4);
#pragma unroll
        for (int r = 0; r < CLS; r++) {
            unsigned ra;
            asm volatile("mapa.shared::cluster.u32 %0, %1, %2;"
                         : "=r"(ra) : "r"(hdst), "r"(r));
            asm volatile("st.shared::cluster.f32 [%0], %1;"
                         :: "r"(ra), "f"(hn));
        }

        cluster_sync_();   // release our stores / acquire peers' stores
    }
}

// ---------------- launch ----------------------------------------------------
extern "C" void kernel_launch(void* const* d_in, const int* in_sizes, int n_in,
                              void* d_out, int out_size)
{
    const float* input = (const float*)d_in[0];   // [T,B,I]
    const float* w_in  = (const float*)d_in[1];   // [I,H]
    const float* w_rec = (const float*)d_in[2];   // [H,H]
    float* out = (float*)d_out;

    int write_last =
        ((size_t)out_size >= (size_t)T_STEPS * BH + (size_t)BH) ? 1 : 0;

    cudaFuncSetAttribute(rnn_scan_kernel,
                         cudaFuncAttributeMaxDynamicSharedMemorySize,
                         SCAN_SMEM_BYTES);

    // x_proj big GEMM
    {
        dim3 grid(HID / GBN, (T_STEPS * BATCH) / GBM);  // (8, 2048)
        xproj_gemm_kernel<<<grid, 256>>>(input, w_in);
    }

    // cluster-parallel sequential scan (16 clusters x 8 CTAs)
    rnn_scan_kernel<<<BATCH / BPC * CLS, 256, SCAN_SMEM_BYTES>>>(
        w_rec, out, write_last);
}

// round 3
// speedup vs baseline: 2.2566x; 1.2453x over previous
#include <cuda_runtime.h>
#include <cstdint>
#include <cstddef>

// Problem constants
#define T_STEPS 2048
#define BATCH   64
#define IN_DIM  256
#define HID     512
#define BH      (BATCH * HID)

// ---------------- scratch (device global; no runtime allocation) -----------
__device__ __align__(128) float g_xproj[(size_t)T_STEPS * BH]; // 256 MiB

// ---------------- Phase A: x_proj GEMM --------------------------------------
#define GBM 64
#define GBN 64
#define GBK 32
#define GTM 4
#define GTN 4

__global__ __launch_bounds__(256) void xproj_gemm_kernel(
    const float* __restrict__ A, const float* __restrict__ B)
{
    __shared__ float As[GBK][GBM];
    __shared__ float Bs[GBK][GBN];

    const int tid = threadIdx.x;
    const int tx = tid % 16;
    const int ty = tid / 16;
    const size_t mBase = (size_t)blockIdx.y * GBM;
    const int    nBase = blockIdx.x * GBN;

    float acc[GTM][GTN];
#pragma unroll
    for (int i = 0; i < GTM; i++)
#pragma unroll
        for (int j = 0; j < GTN; j++) acc[i][j] = 0.0f;

    for (int kt = 0; kt < IN_DIM; kt += GBK) {
#pragma unroll
        for (int s = 0; s < 2; s++) {
            int row = tid / 8 + s * 32;
            int k4  = (tid % 8) * 4;
            float4 v = *(const float4*)&A[(mBase + row) * IN_DIM + kt + k4];
            As[k4 + 0][row] = v.x;
            As[k4 + 1][row] = v.y;
            As[k4 + 2][row] = v.z;
            As[k4 + 3][row] = v.w;
        }
#pragma unroll
        for (int s = 0; s < 2; s++) {
            int row = tid / 16 + s * 16;
            int n4  = (tid % 16) * 4;
            *(float4*)&Bs[row][n4] =
                *(const float4*)&B[(size_t)(kt + row) * HID + nBase + n4];
        }
        __syncthreads();

#pragma unroll
        for (int k = 0; k < GBK; k++) {
            float a[GTM], b[GTN];
            *(float4*)a = *(const float4*)&As[k][ty * GTM];
            *(float4*)b = *(const float4*)&Bs[k][tx * GTN];
#pragma unroll
            for (int i = 0; i < GTM; i++)
#pragma unroll
                for (int j = 0; j < GTN; j++)
                    acc[i][j] += a[i] * b[j];
        }
        __syncthreads();
    }

#pragma unroll
    for (int i = 0; i < GTM; i++) {
        size_t row = mBase + ty * GTM + i;
        float4 v = make_float4(acc[i][0], acc[i][1], acc[i][2], acc[i][3]);
        *(float4*)&g_xproj[row * HID + nBase + tx * GTN] = v;
    }
}

// ---------------- Phase B: cluster scan with st.async + mbarrier ------------
#define CLS  8
#define BPC  4
#define JPC  64
#define NKC  16
#define KC   (HID / NKC)      // 32
#define HPAD 516              // padded h row stride (float4-aligned, staggers banks)

// smem layout (floats)
#define WS_OFF   0
#define WS_FLOATS (HID * JPC)                 // 32768 (128 KB)
#define HS_OFF   (WS_OFF + WS_FLOATS)
#define HS_FLOATS (2 * BPC * HPAD)            // 4128
#define RED_OFF  (HS_OFF + HS_FLOATS)
#define RED_FLOATS (NKC * 256)                // 4096
#define MB_OFF   (RED_OFF + RED_FLOATS)       // 2 x u64 mbarriers
#define SCAN_SMEM_FLOATS (MB_OFF + 8)
#define SCAN_SMEM_BYTES  (SCAN_SMEM_FLOATS * 4)

#define TX_BYTES_PER_PHASE (CLS * 256 * 4)    // 8192: 256 values from each of 8 CTAs

__device__ __forceinline__ void cluster_sync_() {
    asm volatile("barrier.cluster.arrive.aligned;" ::: "memory");
    asm volatile("barrier.cluster.wait.aligned;"   ::: "memory");
}

__device__ __forceinline__ void mbar_init_(unsigned a, unsigned cnt) {
    asm volatile("mbarrier.init.shared.b64 [%0], %1;" :: "r"(a), "r"(cnt) : "memory");
}
__device__ __forceinline__ void mbar_expect_tx_(unsigned a, unsigned bytes) {
    asm volatile("mbarrier.arrive.expect_tx.shared.b64 _, [%0], %1;"
                 :: "r"(a), "r"(bytes) : "memory");
}
__device__ __forceinline__ void mbar_wait_(unsigned a, unsigned parity) {
    unsigned done;
    asm volatile(
        "{\n\t.reg .pred p;\n\t"
        "mbarrier.try_wait.parity.acquire.cta.shared::cta.b64 p, [%1], %2;\n\t"
        "selp.b32 %0, 1, 0, p;\n\t}"
        : "=r"(done) : "r"(a), "r"(parity) : "memory");
    if (!done) {
        asm volatile(
            "{\n\t.reg .pred P1;\n\t"
            "WL_%=:\n\t"
            "mbarrier.try_wait.parity.acquire.cta.shared::cta.b64 P1, [%0], %1, 0x989680;\n\t"
            "@P1 bra.uni WD_%=;\n\t"
            "bra.uni WL_%=;\n\t"
            "WD_%=:\n\t}"
            :: "r"(a), "r"(parity) : "memory");
    }
}
__device__ __forceinline__ void st_async_f32_(unsigned raddr, float v, unsigned rmbar) {
    asm volatile(
        "st.async.shared::cluster.mbarrier::complete_tx::bytes.b32 [%0], %1, [%2];"
        :: "r"(raddr), "r"(__float_as_int(v)), "r"(rmbar) : "memory");
}
__device__ __forceinline__ unsigned long long fma2_(
    unsigned long long a, unsigned long long b, unsigned long long c) {
    unsigned long long d;
    asm("fma.rn.f32x2 %0, %1, %2, %3;" : "=l"(d) : "l"(a), "l"(b), "l"(c));
    return d;
}
__device__ __forceinline__ unsigned long long pack2_(float x) {
    unsigned long long d;
    asm("mov.b64 %0, {%1, %1};" : "=l"(d) : "r"(__float_as_int(x)));
    return d;
}

__global__ __launch_bounds__(256, 1) __cluster_dims__(CLS, 1, 1)
void rnn_scan_kernel(const float* __restrict__ w_rec,
                     float* __restrict__ out, int write_last)
{
    extern __shared__ float smem[];
    float* ws  = smem + WS_OFF;   // [HID][JPC]
    float* hs  = smem + HS_OFF;   // [2][BPC][HPAD]
    float* red = smem + RED_OFF;  // [NKC][256]

    const int tid  = threadIdx.x;
    const int rank = blockIdx.x & (CLS - 1);
    const int b0   = (blockIdx.x >> 3) * BPC;
    const int j0   = rank * JPC;

    const int kc = tid >> 4;      // 0..15 k-chunk
    const int jg = tid & 15;      // 0..15 j-group (4 cols)
    const int ob = tid >> 6;      // 0..3  output batch
    const int oj = tid & 63;      // 0..63 output column

    // ---- prologue ----
    {
        const float4* wsrc = (const float4*)w_rec;
        float4* wdst = (float4*)ws;
        for (int i = tid; i < HID * (JPC / 4); i += 256) {
            int row = i >> 4;
            int c4  = i & 15;
            wdst[row * 16 + c4] = wsrc[row * (HID / 4) + (j0 >> 2) + c4];
        }
        for (int i = tid; i < HS_FLOATS; i += 256) hs[i] = 0.0f;
        if (tid == 0) {
            unsigned mb = (unsigned)__cvta_generic_to_shared(smem + MB_OFF);
            mbar_init_(mb, 1);
            mbar_init_(mb + 8, 1);
        }
    }
    __syncthreads();
    cluster_sync_();   // peers' smem + mbarriers live before any st.async

    // precompute peer base addresses (cluster windows)
    const unsigned hs_loc = (unsigned)__cvta_generic_to_shared(hs);
    const unsigned mb_loc = (unsigned)__cvta_generic_to_shared(smem + MB_OFF);
    unsigned peer_hs[CLS], peer_mb[CLS];
#pragma unroll
    for (int r = 0; r < CLS; r++) {
        asm("mapa.shared::cluster.u32 %0, %1, %2;" : "=r"(peer_hs[r]) : "r"(hs_loc), "r"(r));
        asm("mapa.shared::cluster.u32 %0, %1, %2;" : "=r"(peer_mb[r]) : "r"(mb_loc), "r"(r));
    }

    const float* wrow = ws + (kc * KC) * JPC + jg * 4;
    const size_t xbase = (size_t)(b0 + ob) * HID + j0 + oj;
    const unsigned st_off_base = (unsigned)((ob * HPAD + j0 + oj) * 4);

    int par0 = 0, par1 = 0;

#pragma unroll 1
    for (int t = 0; t < T_STEPS; t++) {
        const int q  = t & 1;
        const int qn = q ^ 1;

        // prefetch this step's input projection (independent of the wait)
        float xv = __ldg(&g_xproj[(size_t)t * BH + xbase]);

        if (t > 0) {
            if (q == 0) { mbar_wait_(mb_loc,     par0); par0 ^= 1; }
            else        { mbar_wait_(mb_loc + 8, par1); par1 ^= 1; }
        }
        // arm next phase's transaction count (a full compute-step of margin)
        if (tid == 0 && t < T_STEPS - 1)
            mbar_expect_tx_(mb_loc + (unsigned)qn * 8, TX_BYTES_PER_PHASE);

        // ---- split-K register-tiled partial products (f32x2 packed) ----
        const float* hp = hs + q * BPC * HPAD + kc * KC;

        unsigned long long acc2[BPC][2];
#pragma unroll
        for (int b = 0; b < BPC; b++) { acc2[b][0] = 0ull; acc2[b][1] = 0ull; }

#pragma unroll
        for (int ki = 0; ki < KC; ki += 4) {
            ulonglong2 w0 = *(const ulonglong2*)(wrow + (ki + 0) * JPC);
            ulonglong2 w1 = *(const ulonglong2*)(wrow + (ki + 1) * JPC);
            ulonglong2 w2 = *(const ulonglong2*)(wrow + (ki + 2) * JPC);
            ulonglong2 w3 = *(const ulonglong2*)(wrow + (ki + 3) * JPC);
#pragma unroll
            for (int b = 0; b < BPC; b++) {
                float4 h4 = *(const float4*)(hp + b * HPAD + ki);
                unsigned long long hh;
                hh = pack2_(h4.x);
                acc2[b][0] = fma2_(hh, w0.x, acc2[b][0]);
                acc2[b][1] = fma2_(hh, w0.y, acc2[b][1]);
                hh = pack2_(h4.y);
                acc2[b][0] = fma2_(hh, w1.x, acc2[b][0]);
                acc2[b][1] = fma2_(hh, w1.y, acc2[b][1]);
                hh = pack2_(h4.z);
                acc2[b][0] = fma2_(hh, w2.x, acc2[b][0]);
                acc2[b][1] = fma2_(hh, w2.y, acc2[b][1]);
                hh = pack2_(h4.w);
                acc2[b][0] = fma2_(hh, w3.x, acc2[b][0]);
                acc2[b][1] = fma2_(hh, w3.y, acc2[b][1]);
            }
        }

#pragma unroll
        for (int b = 0; b < BPC; b++) {
            float2 p0 = *(float2*)&acc2[b][0];
            float2 p1 = *(float2*)&acc2[b][1];
            *(float4*)&red[kc * 256 + b * 64 + jg * 4] =
                make_float4(p0.x, p0.y, p1.x, p1.y);
        }
        __syncthreads();

        // ---- reduce over 16 k-chunks, activate ----
        float s = 0.0f;
#pragma unroll
        for (int c = 0; c < NKC; c++) s += red[c * 256 + tid];
        float hn = tanhf(xv + s);

        out[(size_t)t * BH + xbase] = hn;
        if (write_last && t == T_STEPS - 1)
            out[(size_t)T_STEPS * BH + xbase] = hn;

        // ---- broadcast h_{t+1} via st.async (signals receivers' mbarriers) --
        if (t < T_STEPS - 1) {
            unsigned doff = (unsigned)(qn * BPC * HPAD * 4) + st_off_base;
            unsigned moff = (unsigned)qn * 8;
#pragma unroll
            for (int r = 0; r < CLS; r++)
                st_async_f32_(peer_hs[r] + doff, hn, peer_mb[r] + moff);
        }
    }
    cluster_sync_();   // don't let a CTA exit while peers may still target it
}

// ---------------- launch ----------------------------------------------------
extern "C" void kernel_launch(void* const* d_in, const int* in_sizes, int n_in,
                              void* d_out, int out_size)
{
    const float* input = (const float*)d_in[0];   // [T,B,I]
    const float* w_in  = (const float*)d_in[1];   // [I,H]
    const float* w_rec = (const float*)d_in[2];   // [H,H]
    float* out = (float*)d_out;

    int write_last =
        ((size_t)out_size >= (size_t)T_STEPS * BH + (size_t)BH) ? 1 : 0;

    cudaFuncSetAttribute(rnn_scan_kernel,
                         cudaFuncAttributeMaxDynamicSharedMemorySize,
                         SCAN_SMEM_BYTES);

    {
        dim3 grid(HID / GBN, (T_STEPS * BATCH) / GBM);  // (8, 2048)
        xproj_gemm_kernel<<<grid, 256>>>(input, w_in);
    }

    rnn_scan_kernel<<<BATCH / BPC * CLS, 256, SCAN_SMEM_BYTES>>>(
        w_rec, out, write_last);
}

// round 4
// speedup vs baseline: 2.2576x; 1.0005x over previous
#include <cuda_runtime.h>
#include <cstdint>
#include <cstddef>

// Problem constants
#define T_STEPS 2048
#define BATCH   64
#define IN_DIM  256
#define HID     512
#define BH      (BATCH * HID)

// ---------------- scratch (device global; no runtime allocation) -----------
__device__ __align__(128) float g_xproj[(size_t)T_STEPS * BH]; // 256 MiB

// ---------------- Phase A: x_proj GEMM --------------------------------------
#define GBM 64
#define GBN 64
#define GBK 32
#define GTM 4
#define GTN 4

__global__ __launch_bounds__(256) void xproj_gemm_kernel(
    const float* __restrict__ A, const float* __restrict__ B)
{
    __shared__ float As[GBK][GBM];
    __shared__ float Bs[GBK][GBN];

    const int tid = threadIdx.x;
    const int tx = tid % 16;
    const int ty = tid / 16;
    const size_t mBase = (size_t)blockIdx.y * GBM;
    const int    nBase = blockIdx.x * GBN;

    float acc[GTM][GTN];
#pragma unroll
    for (int i = 0; i < GTM; i++)
#pragma unroll
        for (int j = 0; j < GTN; j++) acc[i][j] = 0.0f;

    for (int kt = 0; kt < IN_DIM; kt += GBK) {
#pragma unroll
        for (int s = 0; s < 2; s++) {
            int row = tid / 8 + s * 32;
            int k4  = (tid % 8) * 4;
            float4 v = *(const float4*)&A[(mBase + row) * IN_DIM + kt + k4];
            As[k4 + 0][row] = v.x;
            As[k4 + 1][row] = v.y;
            As[k4 + 2][row] = v.z;
            As[k4 + 3][row] = v.w;
        }
#pragma unroll
        for (int s = 0; s < 2; s++) {
            int row = tid / 16 + s * 16;
            int n4  = (tid % 16) * 4;
            *(float4*)&Bs[row][n4] =
                *(const float4*)&B[(size_t)(kt + row) * HID + nBase + n4];
        }
        __syncthreads();

#pragma unroll
        for (int k = 0; k < GBK; k++) {
            float a[GTM], b[GTN];
            *(float4*)a = *(const float4*)&As[k][ty * GTM];
            *(float4*)b = *(const float4*)&Bs[k][tx * GTN];
#pragma unroll
            for (int i = 0; i < GTM; i++)
#pragma unroll
                for (int j = 0; j < GTN; j++)
                    acc[i][j] += a[i] * b[j];
        }
        __syncthreads();
    }

#pragma unroll
    for (int i = 0; i < GTM; i++) {
        size_t row = mBase + ty * GTM + i;
        float4 v = make_float4(acc[i][0], acc[i][1], acc[i][2], acc[i][3]);
        *(float4*)&g_xproj[row * HID + nBase + tx * GTN] = v;
    }
}

// ---------------- Phase B: cluster scan with st.async + mbarrier ------------
#define CLS  8
#define BPC  4
#define JPC  64
#define NKC  16
#define KC   (HID / NKC)      // 32
#define HPAD 516              // padded h row stride (float4-aligned, staggers banks)

// smem layout (floats)
#define WS_OFF   0
#define WS_FLOATS (HID * JPC)                 // 32768 (128 KB)
#define HS_OFF   (WS_OFF + WS_FLOATS)
#define HS_FLOATS (2 * BPC * HPAD)            // 4128
#define RED_OFF  (HS_OFF + HS_FLOATS)
#define RED_FLOATS (NKC * 256)                // 4096
#define MB_OFF   (RED_OFF + RED_FLOATS)       // 2 x u64 mbarriers
#define SCAN_SMEM_FLOATS (MB_OFF + 8)
#define SCAN_SMEM_BYTES  (SCAN_SMEM_FLOATS * 4)

#define TX_BYTES_PER_PHASE (CLS * 256 * 4)    // 8192: 256 values from each of 8 CTAs

__device__ __forceinline__ void cluster_sync_() {
    asm volatile("barrier.cluster.arrive.aligned;" ::: "memory");
    asm volatile("barrier.cluster.wait.aligned;"   ::: "memory");
}

__device__ __forceinline__ void mbar_init_(unsigned a, unsigned cnt) {
    asm volatile("mbarrier.init.shared.b64 [%0], %1;" :: "r"(a), "r"(cnt) : "memory");
}
__device__ __forceinline__ void mbar_expect_tx_(unsigned a, unsigned bytes) {
    asm volatile("mbarrier.arrive.expect_tx.shared.b64 _, [%0], %1;"
                 :: "r"(a), "r"(bytes) : "memory");
}
__device__ __forceinline__ void mbar_wait_(unsigned a, unsigned parity) {
    unsigned done;
    asm volatile(
        "{\n\t.reg .pred p;\n\t"
        "mbarrier.try_wait.parity.acquire.cta.shared::cta.b64 p, [%1], %2;\n\t"
        "selp.b32 %0, 1, 0, p;\n\t}"
        : "=r"(done) : "r"(a), "r"(parity) : "memory");
    if (!done) {
        asm volatile(
            "{\n\t.reg .pred P1;\n\t"
            "WL_%=:\n\t"
            "mbarrier.try_wait.parity.acquire.cta.shared::cta.b64 P1, [%0], %1, 0x989680;\n\t"
            "@P1 bra.uni WD_%=;\n\t"
            "bra.uni WL_%=;\n\t"
            "WD_%=:\n\t}"
            :: "r"(a), "r"(parity) : "memory");
    }
}
__device__ __forceinline__ void st_async_f32_(unsigned raddr, float v, unsigned rmbar) {
    asm volatile(
        "st.async.shared::cluster.mbarrier::complete_tx::bytes.b32 [%0], %1, [%2];"
        :: "r"(raddr), "r"(__float_as_int(v)), "r"(rmbar) : "memory");
}
__device__ __forceinline__ unsigned long long fma2_(
    unsigned long long a, unsigned long long b, unsigned long long c) {
    unsigned long long d;
    asm("fma.rn.f32x2 %0, %1, %2, %3;" : "=l"(d) : "l"(a), "l"(b), "l"(c));
    return d;
}
__device__ __forceinline__ unsigned long long pack2_(float x) {
    unsigned long long d;
    asm("mov.b64 %0, {%1, %1};" : "=l"(d) : "r"(__float_as_int(x)));
    return d;
}

__global__ __launch_bounds__(256, 1) __cluster_dims__(CLS, 1, 1)
void rnn_scan_kernel(const float* __restrict__ w_rec,
                     float* __restrict__ out, int write_last)
{
    extern __shared__ float smem[];
    float* ws  = smem + WS_OFF;   // [HID][JPC]
    float* hs  = smem + HS_OFF;   // [2][BPC][HPAD]
    float* red = smem + RED_OFF;  // [NKC][256]

    const int tid  = threadIdx.x;
    const int rank = blockIdx.x & (CLS - 1);
    const int b0   = (blockIdx.x >> 3) * BPC;
    const int j0   = rank * JPC;

    const int kc = tid >> 4;      // 0..15 k-chunk
    const int jg = tid & 15;      // 0..15 j-group (4 cols)
    const int ob = tid >> 6;      // 0..3  output batch
    const int oj = tid & 63;      // 0..63 output column

    // ---- prologue ----
    {
        const float4* wsrc = (const float4*)w_rec;
        float4* wdst = (float4*)ws;
        for (int i = tid; i < HID * (JPC / 4); i += 256) {
            int row = i >> 4;
            int c4  = i & 15;
            wdst[row * 16 + c4] = wsrc[row * (HID / 4) + (j0 >> 2) + c4];
        }
        for (int i = tid; i < HS_FLOATS; i += 256) hs[i] = 0.0f;
        if (tid == 0) {
            unsigned mb = (unsigned)__cvta_generic_to_shared(smem + MB_OFF);
            mbar_init_(mb, 1);
            mbar_init_(mb + 8, 1);
        }
    }
    __syncthreads();
    cluster_sync_();   // peers' smem + mbarriers live before any st.async

    // precompute peer base addresses (cluster windows)
    const unsigned hs_loc = (unsigned)__cvta_generic_to_shared(hs);
    const unsigned mb_loc = (unsigned)__cvta_generic_to_shared(smem + MB_OFF);
    unsigned peer_hs[CLS], peer_mb[CLS];
#pragma unroll
    for (int r = 0; r < CLS; r++) {
        asm("mapa.shared::cluster.u32 %0, %1, %2;" : "=r"(peer_hs[r]) : "r"(hs_loc), "r"(r));
        asm("mapa.shared::cluster.u32 %0, %1, %2;" : "=r"(peer_mb[r]) : "r"(mb_loc), "r"(r));
    }

    const float* wrow = ws + (kc * KC) * JPC + jg * 4;
    const size_t xbase = (size_t)(b0 + ob) * HID + j0 + oj;
    const unsigned st_off_base = (unsigned)((ob * HPAD + j0 + oj) * 4);

    int par0 = 0, par1 = 0;

#pragma unroll 1
    for (int t = 0; t < T_STEPS; t++) {
        const int q  = t & 1;
        const int qn = q ^ 1;

        // prefetch this step's input projection (independent of the wait)
        float xv = __ldg(&g_xproj[(size_t)t * BH + xbase]);

        if (t > 0) {
            if (q == 0) { mbar_wait_(mb_loc,     par0); par0 ^= 1; }
            else        { mbar_wait_(mb_loc + 8, par1); par1 ^= 1; }
        }
        // arm next phase's transaction count (a full compute-step of margin)
        if (tid == 0 && t < T_STEPS - 1)
            mbar_expect_tx_(mb_loc + (unsigned)qn * 8, TX_BYTES_PER_PHASE);

        // ---- split-K register-tiled partial products (f32x2 packed) ----
        const float* hp = hs + q * BPC * HPAD + kc * KC;

        unsigned long long acc2[BPC][2];
#pragma unroll
        for (int b = 0; b < BPC; b++) { acc2[b][0] = 0ull; acc2[b][1] = 0ull; }

#pragma unroll
        for (int ki = 0; ki < KC; ki += 4) {
            ulonglong2 w0 = *(const ulonglong2*)(wrow + (ki + 0) * JPC);
            ulonglong2 w1 = *(const ulonglong2*)(wrow + (ki + 1) * JPC);
            ulonglong2 w2 = *(const ulonglong2*)(wrow + (ki + 2) * JPC);
            ulonglong2 w3 = *(const ulonglong2*)(wrow + (ki + 3) * JPC);
#pragma unroll
            for (int b = 0; b < BPC; b++) {
                float4 h4 = *(const float4*)(hp + b * HPAD + ki);
                unsigned long long hh;
                hh = pack2_(h4.x);
                acc2[b][0] = fma2_(hh, w0.x, acc2[b][0]);
                acc2[b][1] = fma2_(hh, w0.y, acc2[b][1]);
                hh = pack2_(h4.y);
                acc2[b][0] = fma2_(hh, w1.x, acc2[b][0]);
                acc2[b][1] = fma2_(hh, w1.y, acc2[b][1]);
                hh = pack2_(h4.z);
                acc2[b][0] = fma2_(hh, w2.x, acc2[b][0]);
                acc2[b][1] = fma2_(hh, w2.y, acc2[b][1]);
                hh = pack2_(h4.w);
                acc2[b][0] = fma2_(hh, w3.x, acc2[b][0]);
                acc2[b][1] = fma2_(hh, w3.y, acc2[b][1]);
            }
        }

#pragma unroll
        for (int b = 0; b < BPC; b++) {
            float2 p0 = *(float2*)&acc2[b][0];
            float2 p1 = *(float2*)&acc2[b][1];
            *(float4*)&red[kc * 256 + b * 64 + jg * 4] =
                make_float4(p0.x, p0.y, p1.x, p1.y);
        }
        __syncthreads();

        // ---- reduce over 16 k-chunks, activate ----
        float s = 0.0f;
#pragma unroll
        for (int c = 0; c < NKC; c++) s += red[c * 256 + tid];
        float hn = tanhf(xv + s);

        out[(size_t)t * BH + xbase] = hn;
        if (write_last && t == T_STEPS - 1)
            out[(size_t)T_STEPS * BH + xbase] = hn;

        // ---- broadcast h_{t+1} via st.async (signals receivers' mbarriers) --
        if (t < T_STEPS - 1) {
            unsigned doff = (unsigned)(qn * BPC * HPAD * 4) + st_off_base;
            unsigned moff = (unsigned)qn * 8;
#pragma unroll
            for (int r = 0; r < CLS; r++)
                st_async_f32_(peer_hs[r] + doff, hn, peer_mb[r] + moff);
        }
    }
    cluster_sync_();   // don't let a CTA exit while peers may still target it
}

// ---------------- launch ----------------------------------------------------
extern "C" void kernel_launch(void* const* d_in, const int* in_sizes, int n_in,
                              void* d_out, int out_size)
{
    const float* input = (const float*)d_in[0];   // [T,B,I]
    const float* w_in  = (const float*)d_in[1];   // [I,H]
    const float* w_rec = (const float*)d_in[2];   // [H,H]
    float* out = (float*)d_out;

    int write_last =
        ((size_t)out_size >= (size_t)T_STEPS * BH + (size_t)BH) ? 1 : 0;

    cudaFuncSetAttribute(rnn_scan_kernel,
                         cudaFuncAttributeMaxDynamicSharedMemorySize,
                         SCAN_SMEM_BYTES);

    {
        dim3 grid(HID / GBN, (T_STEPS * BATCH) / GBM);  // (8, 2048)
        xproj_gemm_kernel<<<grid, 256>>>(input, w_in);
    }

    rnn_scan_kernel<<<BATCH / BPC * CLS, 256, SCAN_SMEM_BYTES>>>(
        w_rec, out, write_last);
}